// round 14
// baseline (speedup 1.0000x reference)
#include <cuda_runtime.h>
#include <cuda_fp16.h>
#include <cstdint>

// ---------------- problem constants ----------------
#define SEQ    2048
#define DIMN   1024
#define BATCH  2
#define MR     4096            // BATCH*SEQ

// ---------------- GEMM tiling ----------------
#define BM 128
#define BN 128
#define BK 32                  // 32 halves/row-slice; rows [hi 64B | lo 64B]
#define NTHREADS 128           // 4 warps: 2 (m) x 2 (n), warp tile 64x64

#define TILEB  (BM * 128)              // 16384 B per operand tile (hi+lo packed)
#define STAGE  (2 * TILEB)             // A tile + B tile = 32768 B
#define NSTAGE 3
#define SMEM_BYTES (NSTAGE * STAGE)    // 98304 B -> 2 CTAs/SM

#define PV_SCALE 1024.0f               // P stored as fp16 * 2^10
#define PV_INV   (1.0f / 1024.0f)

// ---------------- scratch (__device__ globals; no allocs allowed) ----------------
static __device__ __half g_xh[MR * DIMN],  g_xl[MR * DIMN];
static __device__ __half g_wh[4][DIMN * DIMN], g_wl[4][DIMN * DIMN]; // q,k,v,o
static __device__ __half g_qh[MR * DIMN],  g_ql[MR * DIMN];
static __device__ __half g_kh[MR * DIMN],  g_kl[MR * DIMN];
static __device__ __half g_vTh[MR * DIMN];                          // [B][D][S]
static __device__ float  g_s[BATCH * SEQ * SEQ];
static __device__ __half g_p[BATCH * SEQ * SEQ];                    // fp16, *1024
static __device__ __half g_o[MR * DIMN];                            // fp16 O

// ---------------- helpers ----------------
__device__ __forceinline__ uint32_t smem_u32(const void* p) {
    uint32_t a;
    asm("{ .reg .u64 t; cvta.to.shared.u64 t, %1; cvt.u32.u64 %0, t; }"
        : "=r"(a) : "l"(p));
    return a;
}

__device__ __forceinline__ void cp16(uint32_t saddr, const void* g) {
    asm volatile("cp.async.cg.shared.global [%0], [%1], 16;"
                 :: "r"(saddr), "l"(g) : "memory");
}

__device__ __forceinline__ void ldsm4(uint32_t* r, uint32_t addr) {
    asm volatile("ldmatrix.sync.aligned.m8n8.x4.shared.b16 {%0,%1,%2,%3}, [%4];"
                 : "=r"(r[0]), "=r"(r[1]), "=r"(r[2]), "=r"(r[3])
                 : "r"(addr));
}

__device__ __forceinline__ void mma_f16(float* d, const uint32_t* a,
                                        uint32_t b0, uint32_t b1) {
    asm volatile(
        "mma.sync.aligned.m16n8k16.row.col.f32.f16.f16.f32 "
        "{%0,%1,%2,%3}, {%4,%5,%6,%7}, {%8,%9}, {%0,%1,%2,%3};"
        : "+f"(d[0]), "+f"(d[1]), "+f"(d[2]), "+f"(d[3])
        : "r"(a[0]), "r"(a[1]), "r"(a[2]), "r"(a[3]), "r"(b0), "r"(b1));
}

__device__ __forceinline__ uint32_t sw128(uint32_t x) {
    return x ^ ((x >> 3) & 0x70);   // 128B-row xor swizzle
}

__device__ __forceinline__ __half2 split_pair(float v0, float v1, __half2& lo) {
    __half h0 = __float2half_rn(v0);
    __half h1 = __float2half_rn(v1);
    lo = __halves2half2(__float2half_rn(v0 - __half2float(h0)),
                        __float2half_rn(v1 - __half2float(h1)));
    return __halves2half2(h0, h1);
}

// ----------------------------------------------------------------------------
// Multi-pass fp16 GEMM via mma.sync m16n8k16:  C[M,N] = A[M,K] @ B[N,K]^T
// 128 threads, 4 warps (2m x 2n), warp tile 64x64, 2 CTAs/SM.
// PASS-MAJOR MMA ORDER: each pass sweeps all 32 (mt,nt) accumulators before
// any accumulator is revisited -> no back-to-back RAW on the same acc, the
// tensor pipe issues without dependency stalls (was the 57%-tensor limiter).
// NPASS = 3: hh + lh + hl   NPASS = 2: hh + hl   NPASS = 1: hh only
// EPI: 0 = fp32 store (+bias)   1 = split hi/lo fp16 (+bias)
//      2 = fp16 hi-only transposed [b][n][t] (+bias)   3 = fp16 * PV_INV
// ----------------------------------------------------------------------------
template <int NPASS, int EPI>
__global__ void __launch_bounds__(NTHREADS, 2)
gemm_mp(const __half* __restrict__ Ah, const __half* __restrict__ Al,
        const __half* __restrict__ Bh, const __half* __restrict__ Bl,
        const float* __restrict__ bias,
        void* __restrict__ C0v, void* __restrict__ C1v,
        int M, int N, int K,
        long long sA, long long sB, long long sC)
{
    extern __shared__ char dsmem[];
    const uint32_t sbase = smem_u32(dsmem);

    const int tid  = threadIdx.x;
    const int lane = tid & 31;
    const int wid  = tid >> 5;
    const int wm   = wid >> 1;        // 0..1 (m warp row, 64 rows)
    const int wn   = wid & 1;         // 0..1 (n warp col, 64 cols)

    const int m0 = blockIdx.y * BM;
    const int n0 = blockIdx.x * BN;
    const int bz = blockIdx.z;

    const __half* pAh = Ah + (long long)bz * sA;
    const __half* pAl = Al + (long long)bz * sA;
    const __half* pBh = Bh + (long long)bz * sB;
    const __half* pBl = Bl + (long long)bz * sB;

    // ---- cp.async slots: 512 16B hi-chunks per operand tile; 4 per thread
    uint32_t c_hi[4], c_lo[4];
    int      a_g[4], b_g[4];
#pragma unroll
    for (int j = 0; j < 4; j++) {
        int c   = tid + j * NTHREADS;    // 0..511
        int row = c >> 2;                // 0..127
        int cc  = c & 3;                 // 16B chunk within 64B half
        uint32_t raw = (uint32_t)(row * 128 + cc * 16);
        c_hi[j] = sw128(raw);
        c_lo[j] = sw128(raw + 64);
        a_g[j]  = (m0 + row) * K + cc * 8;   // 8 halves per 16B chunk
        b_g[j]  = (n0 + row) * K + cc * 8;
    }

    auto load_tile = [&](int kt, int s) {
        const int k0 = kt * BK;
        const uint32_t stA = sbase + (uint32_t)s * STAGE;
        const uint32_t stB = stA + TILEB;
#pragma unroll
        for (int j = 0; j < 4; j++) {
            cp16(stA + c_hi[j], pAh + a_g[j] + k0);
            if (NPASS == 3)
                cp16(stA + c_lo[j], pAl + a_g[j] + k0);
            cp16(stB + c_hi[j], pBh + b_g[j] + k0);
            if (NPASS >= 2)
                cp16(stB + c_lo[j], pBl + b_g[j] + k0);
        }
        asm volatile("cp.async.commit_group;" ::: "memory");
    };

    // ---- ldmatrix address components
    const int piece = lane >> 3;
    const int pr    = lane & 7;

    int a_row[4];
#pragma unroll
    for (int mt = 0; mt < 4; mt++)
        a_row[mt] = (wm * 64 + mt * 16 + ((piece & 1) << 3) + pr) * 128;
    const int a_ch = (piece >> 1) * 16;   // + ks*32 (hi); raw+64 for lo

    int b_row[4];
#pragma unroll
    for (int nt2 = 0; nt2 < 4; nt2++)
        b_row[nt2] = (wn * 64 + nt2 * 16 + ((piece >> 1) << 3) + pr) * 128;
    const int b_ch = (piece & 1) * 16;

    float acc[4][8][4];
#pragma unroll
    for (int i = 0; i < 4; i++)
#pragma unroll
        for (int j = 0; j < 8; j++)
#pragma unroll
            for (int r = 0; r < 4; r++) acc[i][j][r] = 0.0f;

    const int KT = K / BK;
    load_tile(0, 0);
    load_tile(1, 1);

    int s = 0, sp = 2;
    for (int kt = 0; kt < KT; kt++) {
        if (kt + 1 < KT)
            asm volatile("cp.async.wait_group 1;" ::: "memory");
        else
            asm volatile("cp.async.wait_group 0;" ::: "memory");
        __syncthreads();
        if (kt + 2 < KT) {
            load_tile(kt + 2, sp);
            if (++sp == NSTAGE) sp = 0;
        }

        const uint32_t stA = sbase + (uint32_t)s * STAGE;
        const uint32_t stB = stA + TILEB;
        if (++s == NSTAGE) s = 0;

#pragma unroll
        for (int ks = 0; ks < 2; ks++) {      // each ks = k16 (2 per BK=32)
            uint32_t fAh[4][4], fAl[4][4];
#pragma unroll
            for (int mt = 0; mt < 4; mt++) {
                uint32_t raw = (uint32_t)(a_row[mt] + ks * 32 + a_ch);
                ldsm4(fAh[mt], stA + sw128(raw));
                if (NPASS == 3) ldsm4(fAl[mt], stA + sw128(raw + 64));
            }
            uint32_t fBh[4][4], fBl[4][4];
#pragma unroll
            for (int nt2 = 0; nt2 < 4; nt2++) {
                uint32_t raw = (uint32_t)(b_row[nt2] + ks * 32 + b_ch);
                ldsm4(fBh[nt2], stB + sw128(raw));
                if (NPASS >= 2) ldsm4(fBl[nt2], stB + sw128(raw + 64));
            }
            // ---- pass-major MMA sweeps: no consecutive RAW on any acc ----
#pragma unroll
            for (int mt = 0; mt < 4; mt++)
#pragma unroll
                for (int nt = 0; nt < 8; nt++) {
                    const int nt2 = nt >> 1, hsel = (nt & 1) * 2;
                    mma_f16(acc[mt][nt], fAh[mt],
                            fBh[nt2][hsel], fBh[nt2][hsel + 1]);
                }
            if (NPASS == 3) {
#pragma unroll
                for (int mt = 0; mt < 4; mt++)
#pragma unroll
                    for (int nt = 0; nt < 8; nt++) {
                        const int nt2 = nt >> 1, hsel = (nt & 1) * 2;
                        mma_f16(acc[mt][nt], fAl[mt],
                                fBh[nt2][hsel], fBh[nt2][hsel + 1]);
                    }
            }
            if (NPASS >= 2) {
#pragma unroll
                for (int mt = 0; mt < 4; mt++)
#pragma unroll
                    for (int nt = 0; nt < 8; nt++) {
                        const int nt2 = nt >> 1, hsel = (nt & 1) * 2;
                        mma_f16(acc[mt][nt], fAh[mt],
                                fBl[nt2][hsel], fBl[nt2][hsel + 1]);
                    }
            }
        }
    }

    // ---- epilogue
    const int rbase = m0 + wm * 64 + (lane >> 2);
    const int cbase = n0 + wn * 64 + (lane & 3) * 2;

#pragma unroll
    for (int mt = 0; mt < 4; mt++) {
#pragma unroll
        for (int nt = 0; nt < 8; nt++) {
            const float* d = acc[mt][nt];
            const int col = cbase + nt * 8;
            const long long r0 = rbase + mt * 16;
            const long long r1 = r0 + 8;
            float b0f = 0.0f, b1f = 0.0f;
            if (bias) { b0f = bias[col]; b1f = bias[col + 1]; }

            if (EPI == 0) {
                float* C = (float*)C0v + (long long)bz * sC;
                *reinterpret_cast<float2*>(&C[r0 * N + col]) =
                    make_float2(d[0] + b0f, d[1] + b1f);
                *reinterpret_cast<float2*>(&C[r1 * N + col]) =
                    make_float2(d[2] + b0f, d[3] + b1f);
            } else if (EPI == 1) {
                __half* Ch = (__half*)C0v + (long long)bz * sC;
                __half* Cl = (__half*)C1v + (long long)bz * sC;
                __half2 l0, l1;
                __half2 h0 = split_pair(d[0] + b0f, d[1] + b1f, l0);
                __half2 h1 = split_pair(d[2] + b0f, d[3] + b1f, l1);
                *reinterpret_cast<__half2*>(&Ch[r0 * N + col]) = h0;
                *reinterpret_cast<__half2*>(&Ch[r1 * N + col]) = h1;
                *reinterpret_cast<__half2*>(&Cl[r0 * N + col]) = l0;
                *reinterpret_cast<__half2*>(&Cl[r1 * N + col]) = l1;
            } else if (EPI == 2) {  // v^T hi-only store, layout [b][n][t]
                __half* Ch = (__half*)C0v;
#pragma unroll
                for (int e = 0; e < 4; e++) {
                    const long long mr = (e < 2) ? r0 : r1;
                    const int n = col + (e & 1);
                    const float v = d[e] + ((e & 1) ? b1f : b0f);
                    const long long bb = mr >> 11;      // SEQ rows per batch
                    const long long t  = mr & 2047;
                    Ch[(bb * DIMN + n) * SEQ + t] = __float2half_rn(v);
                }
            } else {  // EPI == 3: fp16 store of acc * PV_INV (undo P scaling)
                __half* C = (__half*)C0v + (long long)bz * sC;
                *reinterpret_cast<__half2*>(&C[r0 * N + col]) =
                    __halves2half2(__float2half_rn(d[0] * PV_INV),
                                   __float2half_rn(d[1] * PV_INV));
                *reinterpret_cast<__half2*>(&C[r1 * N + col]) =
                    __halves2half2(__float2half_rn(d[2] * PV_INV),
                                   __float2half_rn(d[3] * PV_INV));
            }
        }
    }
}

// ----------------------------------------------------------------------------
// Fused fp16 hi/lo split of ALL external inputs (x + 4 weights), one launch.
// ----------------------------------------------------------------------------
#define XN4 (MR * DIMN / 4)        // 1048576 float4s
#define WN4 (DIMN * DIMN / 4)      // 262144 float4s = 2^18
__global__ void __launch_bounds__(256)
split_all(const float* __restrict__ x,  const float* __restrict__ Wq,
          const float* __restrict__ Wk, const float* __restrict__ Wv,
          const float* __restrict__ Wo,
          __half* __restrict__ xh, __half* __restrict__ xl,
          __half* __restrict__ wh, __half* __restrict__ wl)
{
    const int i = blockIdx.x * 256 + threadIdx.x;
    const float* src;
    __half *hi, *lo;
    int off;
    if (i < XN4) {
        src = x; hi = xh; lo = xl; off = i;
    } else {
        const int j = i - XN4;
        const int w = j >> 18;              // WN4 = 2^18
        off = j & (WN4 - 1);
        src = (w == 0) ? Wq : (w == 1) ? Wk : (w == 2) ? Wv : Wo;
        hi = wh + (long long)w * (DIMN * DIMN);
        lo = wl + (long long)w * (DIMN * DIMN);
    }
    float4 v = reinterpret_cast<const float4*>(src)[off];
    __half2 l01, l23;
    __half2 h01 = split_pair(v.x, v.y, l01);
    __half2 h23 = split_pair(v.z, v.w, l23);
    reinterpret_cast<__half2*>(hi)[2 * off]     = h01;
    reinterpret_cast<__half2*>(hi)[2 * off + 1] = h23;
    reinterpret_cast<__half2*>(lo)[2 * off]     = l01;
    reinterpret_cast<__half2*>(lo)[2 * off + 1] = l23;
}

// ----------------------------------------------------------------------------
// theta + softmax; emits fp16 probabilities scaled by 1024 (PV epilogue
// divides back). theta = 0.5 + 0.2*sigmoid(x) + 0.15*tanh(x) + 0.1*relu(x)
// ----------------------------------------------------------------------------
__global__ void __launch_bounds__(256)
theta_softmax(const float* __restrict__ S, __half* __restrict__ P)
{
    const long long ro = (long long)blockIdx.x * SEQ;
    const int tid  = threadIdx.x;
    const int lane = tid & 31;
    const int wid  = tid >> 5;
    __shared__ float red[8];

    float th[8];
    float mx = -1e30f;
#pragma unroll
    for (int j = 0; j < 8; j++) {
        float x = S[ro + tid + j * 256];
        float sg = 1.0f / (1.0f + __expf(-x));
        float t;
        asm("tanh.approx.f32 %0, %1;" : "=f"(t) : "f"(x));
        float v = 0.5f + 0.2f * sg + 0.15f * t + 0.1f * fmaxf(x, 0.0f);
        th[j] = v;
        mx = fmaxf(mx, v);
    }
#pragma unroll
    for (int o = 16; o > 0; o >>= 1)
        mx = fmaxf(mx, __shfl_xor_sync(0xFFFFFFFFu, mx, o));
    if (lane == 0) red[wid] = mx;
    __syncthreads();
    mx = red[0];
#pragma unroll
    for (int w = 1; w < 8; w++) mx = fmaxf(mx, red[w]);
    __syncthreads();

    float sum = 0.0f;
#pragma unroll
    for (int j = 0; j < 8; j++) {
        float e = __expf(th[j] - mx);
        th[j] = e;
        sum += e;
    }
#pragma unroll
    for (int o = 16; o > 0; o >>= 1)
        sum += __shfl_xor_sync(0xFFFFFFFFu, sum, o);
    if (lane == 0) red[wid] = sum;
    __syncthreads();
    sum = red[0];
#pragma unroll
    for (int w = 1; w < 8; w++) sum += red[w];

    const float inv = PV_SCALE / sum;
#pragma unroll
    for (int j = 0; j < 8; j++)
        P[ro + tid + j * 256] = __float2half_rn(th[j] * inv);
}

// ----------------------------------------------------------------------------
// launch — inputs: x, Wq, bq, Wk, bk, Wv, bv, Wo, bo
// ----------------------------------------------------------------------------
extern "C" void kernel_launch(void* const* d_in, const int* in_sizes, int n_in,
                              void* d_out, int out_size)
{
    const float* x  = (const float*)d_in[0];
    const float* Wq = (const float*)d_in[1];
    const float* bq = (const float*)d_in[2];
    const float* Wk = (const float*)d_in[3];
    const float* bk = (const float*)d_in[4];
    const float* Wv = (const float*)d_in[5];
    const float* bv = (const float*)d_in[6];
    const float* Wo = (const float*)d_in[7];
    const float* bo = (const float*)d_in[8];
    float* out = (float*)d_out;

    cudaFuncSetAttribute(gemm_mp<3, 1>, cudaFuncAttributeMaxDynamicSharedMemorySize, SMEM_BYTES);
    cudaFuncSetAttribute(gemm_mp<2, 2>, cudaFuncAttributeMaxDynamicSharedMemorySize, SMEM_BYTES);
    cudaFuncSetAttribute(gemm_mp<3, 0>, cudaFuncAttributeMaxDynamicSharedMemorySize, SMEM_BYTES);
    cudaFuncSetAttribute(gemm_mp<1, 3>, cudaFuncAttributeMaxDynamicSharedMemorySize, SMEM_BYTES);
    cudaFuncSetAttribute(gemm_mp<2, 0>, cudaFuncAttributeMaxDynamicSharedMemorySize, SMEM_BYTES);

#define SYM(ptr, ty, sym) void* ptr##_v; cudaGetSymbolAddress(&ptr##_v, sym); \
    ty* ptr = (ty*)ptr##_v
    SYM(xh, __half, g_xh);  SYM(xl, __half, g_xl);
    SYM(wh, __half, g_wh);  SYM(wl, __half, g_wl);
    SYM(qh, __half, g_qh);  SYM(ql, __half, g_ql);
    SYM(kh, __half, g_kh);  SYM(kl, __half, g_kl);
    SYM(vTh, __half, g_vTh);
    SYM(sS, float, g_s);
    SYM(pP, __half, g_p);
    SYM(oO, __half, g_o);
#undef SYM

    const int WSZ = DIMN * DIMN;
    __half* Wqh = wh + 0 * WSZ; __half* Wql = wl + 0 * WSZ;
    __half* Wkh = wh + 1 * WSZ; __half* Wkl = wl + 1 * WSZ;
    __half* Wvh = wh + 2 * WSZ; __half* Wvl = wl + 2 * WSZ;
    __half* Woh = wh + 3 * WSZ; __half* Wol = wl + 3 * WSZ;

    // one fused split of all external inputs
    split_all<<<(XN4 + 4 * WN4) / 256, 256>>>(x, Wq, Wk, Wv, Wo, xh, xl, wh, wl);

    const long long QS = (long long)SEQ * DIMN;  // q/k/v/o per-batch stride
    const long long SS = (long long)SEQ * SEQ;   // scores per-batch stride

    // projections (batch folded into M, strides 0)
    dim3 gp(DIMN / BN, MR / BM, 1);
    // Q, K: x3 (errors amplified through QK^T and 0.1*relu)
    gemm_mp<3, 1><<<gp, NTHREADS, SMEM_BYTES>>>(xh, xl, Wqh, Wql, bq, qh, ql,
                                                MR, DIMN, DIMN, 0, 0, 0);
    gemm_mp<3, 1><<<gp, NTHREADS, SMEM_BYTES>>>(xh, xl, Wkh, Wkl, bk, kh, kl,
                                                MR, DIMN, DIMN, 0, 0, 0);
    // V: x2 suffices (error ~ fp16 storage quantum, attenuated through P@V)
    gemm_mp<2, 2><<<gp, NTHREADS, SMEM_BYTES>>>(xh, nullptr, Wvh, Wvl, bv,
                                                vTh, nullptr,
                                                MR, DIMN, DIMN, 0, 0, 0);

    // scores S[b] = Q[b] @ K[b]^T : x3
    dim3 gs(SEQ / BN, SEQ / BM, BATCH);
    gemm_mp<3, 0><<<gs, NTHREADS, SMEM_BYTES>>>(qh, ql, kh, kl, nullptr, sS, nullptr,
                                                SEQ, SEQ, DIMN, QS, QS, SS);

    // theta + softmax -> fp16 P (scaled x1024)
    theta_softmax<<<BATCH * SEQ, 256>>>(sS, pP);

    // O[b] = P[b] @ V[b] : x1 (P * V_hi; V_lo drop attenuated by ||P||_2)
    dim3 gpv(DIMN / BN, SEQ / BM, BATCH);
    gemm_mp<1, 3><<<gpv, NTHREADS, SMEM_BYTES>>>(pP, nullptr, vTh, nullptr,
                                                 nullptr, oO, nullptr,
                                                 SEQ, DIMN, SEQ, SS,
                                                 (long long)DIMN * SEQ, QS);

    // out = O @ Wo^T + bo : x2 (O_hi*(W_hi+W_lo))
    gemm_mp<2, 0><<<gp, NTHREADS, SMEM_BYTES>>>(oO, nullptr, Woh, Wol, bo,
                                                out, nullptr,
                                                MR, DIMN, DIMN, 0, 0, 0);
}

// round 16
// speedup vs baseline: 1.0572x; 1.0572x over previous
#include <cuda_runtime.h>
#include <cuda_fp16.h>
#include <cstdint>

// ---------------- problem constants ----------------
#define SEQ    2048
#define DIMN   1024
#define BATCH  2
#define MR     4096            // BATCH*SEQ

// ---------------- GEMM tiling ----------------
#define BM 128
#define BN 128
#define BK 32                  // 32 halves/row-slice; rows [hi 64B | lo 64B]
#define NTHREADS 128           // 4 warps: 2 (m) x 2 (n), warp tile 64x64

#define TILEB  (BM * 128)              // 16384 B per operand tile (hi+lo packed)
#define STAGE  (2 * TILEB)             // A tile + B tile = 32768 B
#define NSTAGE 3
#define SMEM_BYTES (NSTAGE * STAGE)    // 98304 B -> 2 CTAs/SM

#define PV_SCALE 1024.0f               // P stored as fp16 * 2^10
#define PV_INV   (1.0f / 1024.0f)

// ---------------- scratch (__device__ globals; no allocs allowed) ----------------
static __device__ __half g_xh[MR * DIMN],  g_xl[MR * DIMN];
static __device__ __half g_wh[4][DIMN * DIMN], g_wl[4][DIMN * DIMN]; // q,k,v,o
static __device__ __half g_qh[MR * DIMN],  g_ql[MR * DIMN];
static __device__ __half g_kh[MR * DIMN],  g_kl[MR * DIMN];
static __device__ __half g_vTh[MR * DIMN];                          // [B][D][S]
static __device__ float  g_s[BATCH * SEQ * SEQ];
static __device__ __half g_p[BATCH * SEQ * SEQ];                    // fp16, *1024
static __device__ __half g_o[MR * DIMN];                            // fp16 O

// ---------------- helpers ----------------
__device__ __forceinline__ uint32_t smem_u32(const void* p) {
    uint32_t a;
    asm("{ .reg .u64 t; cvta.to.shared.u64 t, %1; cvt.u32.u64 %0, t; }"
        : "=r"(a) : "l"(p));
    return a;
}

__device__ __forceinline__ void cp16(uint32_t saddr, const void* g) {
    asm volatile("cp.async.cg.shared.global [%0], [%1], 16;"
                 :: "r"(saddr), "l"(g) : "memory");
}

__device__ __forceinline__ void ldsm4(uint32_t* r, uint32_t addr) {
    asm volatile("ldmatrix.sync.aligned.m8n8.x4.shared.b16 {%0,%1,%2,%3}, [%4];"
                 : "=r"(r[0]), "=r"(r[1]), "=r"(r[2]), "=r"(r[3])
                 : "r"(addr));
}

__device__ __forceinline__ void mma_f16(float* d, const uint32_t* a,
                                        uint32_t b0, uint32_t b1) {
    asm volatile(
        "mma.sync.aligned.m16n8k16.row.col.f32.f16.f16.f32 "
        "{%0,%1,%2,%3}, {%4,%5,%6,%7}, {%8,%9}, {%0,%1,%2,%3};"
        : "+f"(d[0]), "+f"(d[1]), "+f"(d[2]), "+f"(d[3])
        : "r"(a[0]), "r"(a[1]), "r"(a[2]), "r"(a[3]), "r"(b0), "r"(b1));
}

__device__ __forceinline__ uint32_t sw128(uint32_t x) {
    return x ^ ((x >> 3) & 0x70);   // 128B-row xor swizzle
}

__device__ __forceinline__ __half2 split_pair(float v0, float v1, __half2& lo) {
    __half h0 = __float2half_rn(v0);
    __half h1 = __float2half_rn(v1);
    lo = __halves2half2(__float2half_rn(v0 - __half2float(h0)),
                        __float2half_rn(v1 - __half2float(h1)));
    return __halves2half2(h0, h1);
}

// ----------------------------------------------------------------------------
// Multi-pass fp16 GEMM body (device function):  C[M,N] = A[M,K] @ B[N,K]^T
// 128 threads, 4 warps (2m x 2n), warp tile 64x64.
// Per-warp ks STAGGER: odd warps process k16 steps in order (1,0) so the
// post-barrier ldsm bursts and MMA phases of co-resident warps interleave.
// NPASS = 3: hh + lh + hl   NPASS = 2: hh + hl   NPASS = 1: hh only
// EPI: 0 = fp32 store (+bias)   1 = split hi/lo fp16 (+bias)
//      2 = fp16 hi-only transposed [b][n][t] (+bias)   3 = fp16 * PV_INV
// ----------------------------------------------------------------------------
template <int NPASS, int EPI>
__device__ __forceinline__ void gemm_body(
    const __half* __restrict__ pAh, const __half* __restrict__ pAl,
    const __half* __restrict__ pBh, const __half* __restrict__ pBl,
    const float* __restrict__ bias,
    void* __restrict__ C0v, void* __restrict__ C1v,
    int M, int N, int K, int m0, int n0, char* dsmem)
{
    const uint32_t sbase = smem_u32(dsmem);

    const int tid  = threadIdx.x;
    const int lane = tid & 31;
    const int wid  = tid >> 5;
    const int wm   = wid >> 1;        // 0..1 (m warp row, 64 rows)
    const int wn   = wid & 1;         // 0..1 (n warp col, 64 cols)
    const int ksf  = wid & 1;         // ks order flip for odd warps

    // ---- cp.async slots: 512 16B hi-chunks per operand tile; 4 per thread
    uint32_t c_hi[4], c_lo[4];
    int      a_g[4], b_g[4];
#pragma unroll
    for (int j = 0; j < 4; j++) {
        int c   = tid + j * NTHREADS;    // 0..511
        int row = c >> 2;                // 0..127
        int cc  = c & 3;                 // 16B chunk within 64B half
        uint32_t raw = (uint32_t)(row * 128 + cc * 16);
        c_hi[j] = sw128(raw);
        c_lo[j] = sw128(raw + 64);
        a_g[j]  = (m0 + row) * K + cc * 8;   // 8 halves per 16B chunk
        b_g[j]  = (n0 + row) * K + cc * 8;
    }

    auto load_tile = [&](int kt, int s) {
        const int k0 = kt * BK;
        const uint32_t stA = sbase + (uint32_t)s * STAGE;
        const uint32_t stB = stA + TILEB;
#pragma unroll
        for (int j = 0; j < 4; j++) {
            cp16(stA + c_hi[j], pAh + a_g[j] + k0);
            if (NPASS == 3)
                cp16(stA + c_lo[j], pAl + a_g[j] + k0);
            cp16(stB + c_hi[j], pBh + b_g[j] + k0);
            if (NPASS >= 2)
                cp16(stB + c_lo[j], pBl + b_g[j] + k0);
        }
        asm volatile("cp.async.commit_group;" ::: "memory");
    };

    // ---- ldmatrix address components
    const int piece = lane >> 3;
    const int pr    = lane & 7;

    int a_row[4];
#pragma unroll
    for (int mt = 0; mt < 4; mt++)
        a_row[mt] = (wm * 64 + mt * 16 + ((piece & 1) << 3) + pr) * 128;
    const int a_ch = (piece >> 1) * 16;   // + ks*32 (hi); raw+64 for lo

    int b_row[4];
#pragma unroll
    for (int nt2 = 0; nt2 < 4; nt2++)
        b_row[nt2] = (wn * 64 + nt2 * 16 + ((piece >> 1) << 3) + pr) * 128;
    const int b_ch = (piece & 1) * 16;

    float acc[4][8][4];
#pragma unroll
    for (int i = 0; i < 4; i++)
#pragma unroll
        for (int j = 0; j < 8; j++)
#pragma unroll
            for (int r = 0; r < 4; r++) acc[i][j][r] = 0.0f;

    const int KT = K / BK;
    load_tile(0, 0);
    load_tile(1, 1);

    int s = 0, sp = 2;
    for (int kt = 0; kt < KT; kt++) {
        if (kt + 1 < KT)
            asm volatile("cp.async.wait_group 1;" ::: "memory");
        else
            asm volatile("cp.async.wait_group 0;" ::: "memory");
        __syncthreads();
        if (kt + 2 < KT) {
            load_tile(kt + 2, sp);
            if (++sp == NSTAGE) sp = 0;
        }

        const uint32_t stA = sbase + (uint32_t)s * STAGE;
        const uint32_t stB = stA + TILEB;
        if (++s == NSTAGE) s = 0;

#pragma unroll
        for (int ksi = 0; ksi < 2; ksi++) {   // each ks = k16 (2 per BK=32)
            const int ks = ksi ^ ksf;         // stagger across warps
            uint32_t fAh[4][4], fAl[4][4];
#pragma unroll
            for (int mt = 0; mt < 4; mt++) {
                uint32_t raw = (uint32_t)(a_row[mt] + ks * 32 + a_ch);
                ldsm4(fAh[mt], stA + sw128(raw));
                if (NPASS == 3) ldsm4(fAl[mt], stA + sw128(raw + 64));
            }
            uint32_t fBh[4][4], fBl[4][4];
#pragma unroll
            for (int nt2 = 0; nt2 < 4; nt2++) {
                uint32_t raw = (uint32_t)(b_row[nt2] + ks * 32 + b_ch);
                ldsm4(fBh[nt2], stB + sw128(raw));
                if (NPASS >= 2) ldsm4(fBl[nt2], stB + sw128(raw + 64));
            }
            // ---- pass-major MMA sweeps ----
#pragma unroll
            for (int mt = 0; mt < 4; mt++)
#pragma unroll
                for (int nt = 0; nt < 8; nt++) {
                    const int nt2 = nt >> 1, hsel = (nt & 1) * 2;
                    mma_f16(acc[mt][nt], fAh[mt],
                            fBh[nt2][hsel], fBh[nt2][hsel + 1]);
                }
            if (NPASS == 3) {
#pragma unroll
                for (int mt = 0; mt < 4; mt++)
#pragma unroll
                    for (int nt = 0; nt < 8; nt++) {
                        const int nt2 = nt >> 1, hsel = (nt & 1) * 2;
                        mma_f16(acc[mt][nt], fAl[mt],
                                fBh[nt2][hsel], fBh[nt2][hsel + 1]);
                    }
            }
            if (NPASS >= 2) {
#pragma unroll
                for (int mt = 0; mt < 4; mt++)
#pragma unroll
                    for (int nt = 0; nt < 8; nt++) {
                        const int nt2 = nt >> 1, hsel = (nt & 1) * 2;
                        mma_f16(acc[mt][nt], fAh[mt],
                                fBl[nt2][hsel], fBl[nt2][hsel + 1]);
                    }
            }
        }
    }

    // ---- epilogue
    const int rbase = m0 + wm * 64 + (lane >> 2);
    const int cbase = n0 + wn * 64 + (lane & 3) * 2;

#pragma unroll
    for (int mt = 0; mt < 4; mt++) {
#pragma unroll
        for (int nt = 0; nt < 8; nt++) {
            const float* d = acc[mt][nt];
            const int col = cbase + nt * 8;
            const long long r0 = rbase + mt * 16;
            const long long r1 = r0 + 8;
            float b0f = 0.0f, b1f = 0.0f;
            if (bias) { b0f = bias[col]; b1f = bias[col + 1]; }

            if (EPI == 0) {
                float* C = (float*)C0v;
                *reinterpret_cast<float2*>(&C[r0 * N + col]) =
                    make_float2(d[0] + b0f, d[1] + b1f);
                *reinterpret_cast<float2*>(&C[r1 * N + col]) =
                    make_float2(d[2] + b0f, d[3] + b1f);
            } else if (EPI == 1) {
                __half* Ch = (__half*)C0v;
                __half* Cl = (__half*)C1v;
                __half2 l0, l1;
                __half2 h0 = split_pair(d[0] + b0f, d[1] + b1f, l0);
                __half2 h1 = split_pair(d[2] + b0f, d[3] + b1f, l1);
                *reinterpret_cast<__half2*>(&Ch[r0 * N + col]) = h0;
                *reinterpret_cast<__half2*>(&Ch[r1 * N + col]) = h1;
                *reinterpret_cast<__half2*>(&Cl[r0 * N + col]) = l0;
                *reinterpret_cast<__half2*>(&Cl[r1 * N + col]) = l1;
            } else if (EPI == 2) {  // v^T hi-only store, layout [b][n][t]
                __half* Ch = (__half*)C0v;
#pragma unroll
                for (int e = 0; e < 4; e++) {
                    const long long mr = (e < 2) ? r0 : r1;
                    const int n = col + (e & 1);
                    const float v = d[e] + ((e & 1) ? b1f : b0f);
                    const long long bb = mr >> 11;      // SEQ rows per batch
                    const long long t  = mr & 2047;
                    Ch[(bb * DIMN + n) * SEQ + t] = __float2half_rn(v);
                }
            } else {  // EPI == 3: fp16 store of acc * PV_INV (undo P scaling)
                __half* C = (__half*)C0v;
                *reinterpret_cast<__half2*>(&C[r0 * N + col]) =
                    __halves2half2(__float2half_rn(d[0] * PV_INV),
                                   __float2half_rn(d[1] * PV_INV));
                *reinterpret_cast<__half2*>(&C[r1 * N + col]) =
                    __halves2half2(__float2half_rn(d[2] * PV_INV),
                                   __float2half_rn(d[3] * PV_INV));
            }
        }
    }
}

// ---------------- standalone GEMM kernel ----------------
template <int NPASS, int EPI>
__global__ void __launch_bounds__(NTHREADS, 2)
gemm_mp(const __half* __restrict__ Ah, const __half* __restrict__ Al,
        const __half* __restrict__ Bh, const __half* __restrict__ Bl,
        const float* __restrict__ bias,
        void* __restrict__ C0v, void* __restrict__ C1v,
        int M, int N, int K,
        long long sA, long long sB, long long sC)
{
    extern __shared__ char dsmem[];
    const int bz = blockIdx.z;
    gemm_body<NPASS, EPI>(
        Ah + (long long)bz * sA, Al ? Al + (long long)bz * sA : nullptr,
        Bh + (long long)bz * sB, Bl ? Bl + (long long)bz * sB : nullptr,
        bias,
        (char*)C0v + (long long)bz * sC * (EPI == 0 ? 4 : 2),
        C1v ? (char*)C1v + (long long)bz * sC * 2 : nullptr,
        M, N, K, blockIdx.y * BM, blockIdx.x * BN, dsmem);
}

// ---------------- fused QK-scores + V-projection kernel ----------------
// grid (16,16,3): z<2 -> QK tile for batch z; z==2 -> V-projection tile.
// The 256 V CTAs backfill QK's partial second wave (512+256 over 296 slots).
__global__ void __launch_bounds__(NTHREADS, 2)
gemm_qk_v(const __half* __restrict__ qh, const __half* __restrict__ ql,
          const __half* __restrict__ kh, const __half* __restrict__ kl,
          float* __restrict__ sS,
          const __half* __restrict__ xh,
          const __half* __restrict__ Wvh, const __half* __restrict__ Wvl,
          const float* __restrict__ bv, __half* __restrict__ vTh)
{
    extern __shared__ char dsmem[];
    const int bz = blockIdx.z;
    if (bz < 2) {
        const long long QS = (long long)SEQ * DIMN;
        const long long SS = (long long)SEQ * SEQ;
        gemm_body<3, 0>(qh + bz * QS, ql + bz * QS, kh + bz * QS, kl + bz * QS,
                        nullptr, sS + bz * SS, nullptr,
                        SEQ, SEQ, DIMN,
                        blockIdx.y * BM, blockIdx.x * BN, dsmem);
    } else {
        const int id = blockIdx.y * 16 + blockIdx.x;   // 0..255
        gemm_body<2, 2>(xh, nullptr, Wvh, Wvl, bv, vTh, nullptr,
                        MR, DIMN, DIMN,
                        (id >> 3) * BM, (id & 7) * BN, dsmem);
    }
}

// ----------------------------------------------------------------------------
// Fused fp16 hi/lo split of ALL external inputs (x + 4 weights), one launch.
// ----------------------------------------------------------------------------
#define XN4 (MR * DIMN / 4)        // 1048576 float4s
#define WN4 (DIMN * DIMN / 4)      // 262144 float4s = 2^18
__global__ void __launch_bounds__(256)
split_all(const float* __restrict__ x,  const float* __restrict__ Wq,
          const float* __restrict__ Wk, const float* __restrict__ Wv,
          const float* __restrict__ Wo,
          __half* __restrict__ xh, __half* __restrict__ xl,
          __half* __restrict__ wh, __half* __restrict__ wl)
{
    const int i = blockIdx.x * 256 + threadIdx.x;
    const float* src;
    __half *hi, *lo;
    int off;
    if (i < XN4) {
        src = x; hi = xh; lo = xl; off = i;
    } else {
        const int j = i - XN4;
        const int w = j >> 18;              // WN4 = 2^18
        off = j & (WN4 - 1);
        src = (w == 0) ? Wq : (w == 1) ? Wk : (w == 2) ? Wv : Wo;
        hi = wh + (long long)w * (DIMN * DIMN);
        lo = wl + (long long)w * (DIMN * DIMN);
    }
    float4 v = reinterpret_cast<const float4*>(src)[off];
    __half2 l01, l23;
    __half2 h01 = split_pair(v.x, v.y, l01);
    __half2 h23 = split_pair(v.z, v.w, l23);
    reinterpret_cast<__half2*>(hi)[2 * off]     = h01;
    reinterpret_cast<__half2*>(hi)[2 * off + 1] = h23;
    reinterpret_cast<__half2*>(lo)[2 * off]     = l01;
    reinterpret_cast<__half2*>(lo)[2 * off + 1] = l23;
}

// ----------------------------------------------------------------------------
// theta + softmax; emits fp16 probabilities scaled by 1024 (PV epilogue
// divides back). theta = 0.5 + 0.2*sigmoid(x) + 0.15*tanh(x) + 0.1*relu(x)
// ----------------------------------------------------------------------------
__global__ void __launch_bounds__(256)
theta_softmax(const float* __restrict__ S, __half* __restrict__ P)
{
    const long long ro = (long long)blockIdx.x * SEQ;
    const int tid  = threadIdx.x;
    const int lane = tid & 31;
    const int wid  = tid >> 5;
    __shared__ float red[8];

    float th[8];
    float mx = -1e30f;
#pragma unroll
    for (int j = 0; j < 8; j++) {
        float x = S[ro + tid + j * 256];
        float sg = 1.0f / (1.0f + __expf(-x));
        float t;
        asm("tanh.approx.f32 %0, %1;" : "=f"(t) : "f"(x));
        float v = 0.5f + 0.2f * sg + 0.15f * t + 0.1f * fmaxf(x, 0.0f);
        th[j] = v;
        mx = fmaxf(mx, v);
    }
#pragma unroll
    for (int o = 16; o > 0; o >>= 1)
        mx = fmaxf(mx, __shfl_xor_sync(0xFFFFFFFFu, mx, o));
    if (lane == 0) red[wid] = mx;
    __syncthreads();
    mx = red[0];
#pragma unroll
    for (int w = 1; w < 8; w++) mx = fmaxf(mx, red[w]);
    __syncthreads();

    float sum = 0.0f;
#pragma unroll
    for (int j = 0; j < 8; j++) {
        float e = __expf(th[j] - mx);
        th[j] = e;
        sum += e;
    }
#pragma unroll
    for (int o = 16; o > 0; o >>= 1)
        sum += __shfl_xor_sync(0xFFFFFFFFu, sum, o);
    if (lane == 0) red[wid] = sum;
    __syncthreads();
    sum = red[0];
#pragma unroll
    for (int w = 1; w < 8; w++) sum += red[w];

    const float inv = PV_SCALE / sum;
#pragma unroll
    for (int j = 0; j < 8; j++)
        P[ro + tid + j * 256] = __float2half_rn(th[j] * inv);
}

// ----------------------------------------------------------------------------
// launch — inputs: x, Wq, bq, Wk, bk, Wv, bv, Wo, bo
// ----------------------------------------------------------------------------
extern "C" void kernel_launch(void* const* d_in, const int* in_sizes, int n_in,
                              void* d_out, int out_size)
{
    const float* x  = (const float*)d_in[0];
    const float* Wq = (const float*)d_in[1];
    const float* bq = (const float*)d_in[2];
    const float* Wk = (const float*)d_in[3];
    const float* bk = (const float*)d_in[4];
    const float* Wv = (const float*)d_in[5];
    const float* bv = (const float*)d_in[6];
    const float* Wo = (const float*)d_in[7];
    const float* bo = (const float*)d_in[8];
    float* out = (float*)d_out;

    cudaFuncSetAttribute(gemm_mp<3, 1>, cudaFuncAttributeMaxDynamicSharedMemorySize, SMEM_BYTES);
    cudaFuncSetAttribute(gemm_mp<1, 3>, cudaFuncAttributeMaxDynamicSharedMemorySize, SMEM_BYTES);
    cudaFuncSetAttribute(gemm_mp<2, 0>, cudaFuncAttributeMaxDynamicSharedMemorySize, SMEM_BYTES);
    cudaFuncSetAttribute(gemm_qk_v,     cudaFuncAttributeMaxDynamicSharedMemorySize, SMEM_BYTES);

#define SYM(ptr, ty, sym) void* ptr##_v; cudaGetSymbolAddress(&ptr##_v, sym); \
    ty* ptr = (ty*)ptr##_v
    SYM(xh, __half, g_xh);  SYM(xl, __half, g_xl);
    SYM(wh, __half, g_wh);  SYM(wl, __half, g_wl);
    SYM(qh, __half, g_qh);  SYM(ql, __half, g_ql);
    SYM(kh, __half, g_kh);  SYM(kl, __half, g_kl);
    SYM(vTh, __half, g_vTh);
    SYM(sS, float, g_s);
    SYM(pP, __half, g_p);
    SYM(oO, __half, g_o);
#undef SYM

    const int WSZ = DIMN * DIMN;
    __half* Wqh = wh + 0 * WSZ; __half* Wql = wl + 0 * WSZ;
    __half* Wkh = wh + 1 * WSZ; __half* Wkl = wl + 1 * WSZ;
    __half* Wvh = wh + 2 * WSZ; __half* Wvl = wl + 2 * WSZ;
    __half* Woh = wh + 3 * WSZ; __half* Wol = wl + 3 * WSZ;

    // one fused split of all external inputs
    split_all<<<(XN4 + 4 * WN4) / 256, 256>>>(x, Wq, Wk, Wv, Wo, xh, xl, wh, wl);

    const long long QS = (long long)SEQ * DIMN;  // q/k/v/o per-batch stride
    const long long SS = (long long)SEQ * SEQ;   // scores per-batch stride

    // Q, K projections: x3 (errors amplified through QK^T and 0.1*relu)
    dim3 gp(DIMN / BN, MR / BM, 1);
    gemm_mp<3, 1><<<gp, NTHREADS, SMEM_BYTES>>>(xh, xl, Wqh, Wql, bq, qh, ql,
                                                MR, DIMN, DIMN, 0, 0, 0);
    gemm_mp<3, 1><<<gp, NTHREADS, SMEM_BYTES>>>(xh, xl, Wkh, Wkl, bk, kh, kl,
                                                MR, DIMN, DIMN, 0, 0, 0);

    // fused: QK scores (x3, 512 CTAs) + V projection (x2, 256 CTAs backfill)
    dim3 gqv(SEQ / BN, SEQ / BM, 3);
    gemm_qk_v<<<gqv, NTHREADS, SMEM_BYTES>>>(qh, ql, kh, kl, sS,
                                             xh, Wvh, Wvl, bv, vTh);

    // theta + softmax -> fp16 P (scaled x1024)
    theta_softmax<<<BATCH * SEQ, 256>>>(sS, pP);

    // O[b] = P[b] @ V[b] : x1 (P * V_hi)
    dim3 gpv(DIMN / BN, SEQ / BM, BATCH);
    gemm_mp<1, 3><<<gpv, NTHREADS, SMEM_BYTES>>>(pP, nullptr, vTh, nullptr,
                                                 nullptr, oO, nullptr,
                                                 SEQ, DIMN, SEQ, SS,
                                                 (long long)DIMN * SEQ, QS);

    // out = O @ Wo^T + bo : x2 (O_hi*(W_hi+W_lo))
    gemm_mp<2, 0><<<gp, NTHREADS, SMEM_BYTES>>>(oO, nullptr, Woh, Wol, bo,
                                                out, nullptr,
                                                MR, DIMN, DIMN, 0, 0, 0);
}